// round 3
// baseline (speedup 1.0000x reference)
#include <cuda_runtime.h>
#include <cuda_bf16.h>
#include <cstdint>
#include <cstddef>

// ============================================================================
// LinearDecoder: out_mean = mean @ W^T + b ; out_logv = log( exp(logvar) @ (W*W)^T )
// B=131072, X=128, Y=512.
// Plain-sm_103-PTX implementation (harness compiles PTX at .target sm_103, so
// no tcgen05/"a" features). Uses mma.sync.m16n8k16 bf16 with fp32 hi/lo
// splitting (hh + hl + lh) for fp32-grade accuracy, ldmatrix with XOR swizzle,
// and cp.async double-buffered B tiles.
// ============================================================================

static constexpr int XD  = 128;   // K
static constexpr int YD  = 512;   // N total
static constexpr int MT  = 128;   // M rows per CTA
static constexpr int NC  = 128;   // N per chunk
static constexpr int TPB = 256;

// Prebuilt bf16 tiles of W / W*W: [n_chunk][kind: Whi,Wlo,W2hi,W2lo][32KB]
// Tile layout: 128 rows x 256B, 16B chunks XOR-swizzled: off(r,k) below.
__device__ __align__(16) unsigned char g_Bpre[4][4][32768];

// SMEM layout
static constexpr int OFF_BIAS = 0;                   // 512 floats
static constexpr int OFF_AH   = 4096;                // A hi tile 32KB
static constexpr int OFF_AL   = OFF_AH + 32768;      // A lo tile
static constexpr int OFF_B0   = OFF_AL + 32768;      // B buffer 0 (hi+lo, 64KB)
static constexpr int OFF_B1   = OFF_B0 + 65536;      // B buffer 1
static constexpr int SMEM_SIZE = OFF_B1 + 65536;     // 200704 B

// ---------------------------------------------------------------------------
// helpers
// ---------------------------------------------------------------------------
__device__ __forceinline__ uint32_t smem_u32(const void* p) {
    uint32_t a;
    asm("{ .reg .u64 t; cvta.to.shared.u64 t, %1; cvt.u32.u64 %0, t; }"
        : "=r"(a) : "l"(p));
    return a;
}

// byte offset of bf16 element (row r, even col k0) in a [128 x 128bf16] tile,
// rows of 256B, 16B chunk index XOR-swizzled with (r&7) -> every ldmatrix
// phase (8 rows, same logical chunk) hits 8 distinct 16B bank groups.
__device__ __forceinline__ uint32_t tile_off(int r, int k0) {
    uint32_t ck = (uint32_t)(k0 >> 3) ^ (uint32_t)(r & 7);
    return (uint32_t)r * 256u + ck * 16u + (uint32_t)(k0 & 7) * 2u;
}

__device__ __forceinline__ float bf16rt(float x) {
    return __bfloat162float(__float2bfloat16(x));
}

__device__ __forceinline__ uint32_t pack2(float a, float b) {
    __nv_bfloat162 t = __floats2bfloat162_rn(a, b);
    return *reinterpret_cast<uint32_t*>(&t);
}

__device__ __forceinline__ void cp16(uint32_t dst, const void* src) {
    asm volatile("cp.async.cg.shared.global [%0], [%1], 16;"
                 :: "r"(dst), "l"(src) : "memory");
}
__device__ __forceinline__ void cp_commit() {
    asm volatile("cp.async.commit_group;" ::: "memory");
}
template <int N>
__device__ __forceinline__ void cp_wait() {
    asm volatile("cp.async.wait_group %0;" :: "n"(N) : "memory");
}

__device__ __forceinline__ void ldsm4(uint32_t* r, uint32_t addr) {
    asm volatile("ldmatrix.sync.aligned.m8n8.x4.shared.b16 {%0,%1,%2,%3}, [%4];"
                 : "=r"(r[0]), "=r"(r[1]), "=r"(r[2]), "=r"(r[3]) : "r"(addr));
}

__device__ __forceinline__ void mma16816(float* c, const uint32_t* a,
                                         uint32_t b0, uint32_t b1) {
    asm volatile(
        "mma.sync.aligned.m16n8k16.row.col.f32.bf16.bf16.f32 "
        "{%0,%1,%2,%3}, {%4,%5,%6,%7}, {%8,%9}, {%0,%1,%2,%3};"
        : "+f"(c[0]), "+f"(c[1]), "+f"(c[2]), "+f"(c[3])
        : "r"(a[0]), "r"(a[1]), "r"(a[2]), "r"(a[3]), "r"(b0), "r"(b1));
}

// ---------------------------------------------------------------------------
// Prep kernel: build bf16 hi/lo tiles for W and W*W (runs once per launch)
// ---------------------------------------------------------------------------
__global__ void prep_w_kernel(const float* __restrict__ W) {
    int idx = blockIdx.x * blockDim.x + threadIdx.x;
    if (idx >= YD * (XD / 2)) return;
    int row = idx >> 6;          // 0..511
    int k0  = (idx & 63) * 2;

    float w0 = W[row * XD + k0];
    float w1 = W[row * XD + k0 + 1];
    int chunk = row >> 7;
    int r = row & 127;
    uint32_t sw = tile_off(r, k0);

    float h0 = bf16rt(w0), h1 = bf16rt(w1);
    *(uint32_t*)(&g_Bpre[chunk][0][sw]) = pack2(h0, h1);
    *(uint32_t*)(&g_Bpre[chunk][1][sw]) = pack2(w0 - h0, w1 - h1);

    float s0 = w0 * w0, s1 = w1 * w1;
    float sh0 = bf16rt(s0), sh1 = bf16rt(s1);
    *(uint32_t*)(&g_Bpre[chunk][2][sw]) = pack2(sh0, sh1);
    *(uint32_t*)(&g_Bpre[chunk][3][sw]) = pack2(s0 - sh0, s1 - sh1);
}

// ---------------------------------------------------------------------------
// Main kernel
// ---------------------------------------------------------------------------
__device__ __forceinline__ void prefetch_B(int nc, int branch, uint32_t dst,
                                           int tid) {
    const unsigned char* srcH = g_Bpre[nc][branch * 2];
    const unsigned char* srcL = g_Bpre[nc][branch * 2 + 1];
    #pragma unroll
    for (int i = tid; i < 2048; i += TPB) {
        cp16(dst + i * 16,         srcH + i * 16);
        cp16(dst + 32768 + i * 16, srcL + i * 16);
    }
}

__global__ void __launch_bounds__(TPB)
decoder_kernel(const float* __restrict__ mean, const float* __restrict__ logvar,
               const float* __restrict__ bias,
               float* __restrict__ out_mean, float* __restrict__ out_logv) {
    extern __shared__ __align__(16) char smem[];
    const uint32_t sb = smem_u32(smem);
    const int tid = threadIdx.x;
    const int t   = tid & 31;          // lane
    const int wid = tid >> 5;          // 0..7
    const int wm  = wid & 3;           // warp M group (4 x 32 rows)
    const int wn  = wid >> 2;          // warp N group (2 x 64 cols)
    const int mbase = wm * 32;
    const int nbase = wn * 64;
    const int row0 = blockIdx.x * MT;

    // bias -> smem
    for (int i = tid; i < YD; i += TPB)
        ((float*)(smem + OFF_BIAS))[i] = bias[i];

    for (int branch = 0; branch < 2; ++branch) {
        // ---- A conversion: (mean) or exp(logvar) -> hi/lo bf16 tiles ----
        const float* src = branch ? logvar : mean;
        for (int idx = tid; idx < MT * (XD / 2); idx += TPB) {
            int r  = idx >> 6;
            int k0 = (idx & 63) * 2;
            float2 v = *(const float2*)(src + (size_t)(row0 + r) * XD + k0);
            float v0 = v.x, v1 = v.y;
            if (branch) { v0 = __expf(v0); v1 = __expf(v1); }
            uint32_t sw = tile_off(r, k0);
            float h0 = bf16rt(v0), h1 = bf16rt(v1);
            *(uint32_t*)(smem + OFF_AH + sw) = pack2(h0, h1);
            *(uint32_t*)(smem + OFF_AL + sw) = pack2(v0 - h0, v1 - h1);
        }
        __syncthreads();

        prefetch_B(0, branch, sb + OFF_B0, tid);
        cp_commit();

        for (int nc = 0; nc < 4; ++nc) {
            if (nc < 3) {
                prefetch_B(nc + 1, branch,
                           sb + (((nc + 1) & 1) ? OFF_B1 : OFF_B0), tid);
                cp_commit();
                cp_wait<1>();
            } else {
                cp_wait<0>();
            }
            __syncthreads();

            const uint32_t bbase = sb + ((nc & 1) ? OFF_B1 : OFF_B0);
            float c[2][8][4] = {};

            #pragma unroll
            for (int ks = 0; ks < 8; ++ks) {
                uint32_t ah[8], al[8], bh[16], bl[16];
                // A fragments: rows mbase + mi*16 + (t&15), chunk 2ks + (t>>4)
                #pragma unroll
                for (int mi = 0; mi < 2; ++mi) {
                    uint32_t row = (uint32_t)(mbase + mi * 16 + (t & 15));
                    uint32_t ck  = (uint32_t)(2 * ks + (t >> 4));
                    uint32_t off = row * 256u + ((ck ^ (row & 7u)) << 4);
                    ldsm4(&ah[mi * 4], sb + OFF_AH + off);
                    ldsm4(&al[mi * 4], sb + OFF_AL + off);
                }
                // B fragments: rows nbase + g*16 + (t&7) + ((t&16)>>1)
                #pragma unroll
                for (int g = 0; g < 4; ++g) {
                    uint32_t row = (uint32_t)(nbase + g * 16 + (t & 7) +
                                              ((t & 16) >> 1));
                    uint32_t ck  = (uint32_t)(2 * ks + ((t >> 3) & 1));
                    uint32_t off = row * 256u + ((ck ^ (row & 7u)) << 4);
                    ldsm4(&bh[g * 4], bbase + off);
                    ldsm4(&bl[g * 4], bbase + 32768 + off);
                }
                // 3 split terms: hh, hl, lh
                #pragma unroll
                for (int mi = 0; mi < 2; ++mi) {
                    #pragma unroll
                    for (int ni = 0; ni < 8; ++ni) {
                        const int bi = (ni >> 1) * 4 + (ni & 1) * 2;
                        mma16816(c[mi][ni], &ah[mi * 4], bh[bi], bh[bi + 1]);
                        mma16816(c[mi][ni], &ah[mi * 4], bl[bi], bl[bi + 1]);
                        mma16816(c[mi][ni], &al[mi * 4], bh[bi], bh[bi + 1]);
                    }
                }
            }

            // ---- epilogue ----
            const float* bs = (const float*)(smem + OFF_BIAS);
            #pragma unroll
            for (int mi = 0; mi < 2; ++mi) {
                const int r0 = row0 + mbase + mi * 16 + (t >> 2);
                #pragma unroll
                for (int ni = 0; ni < 8; ++ni) {
                    const int col = nc * NC + nbase + ni * 8 + (t & 3) * 2;
                    float2 v0, v1;
                    v0.x = c[mi][ni][0]; v0.y = c[mi][ni][1];
                    v1.x = c[mi][ni][2]; v1.y = c[mi][ni][3];
                    if (branch == 0) {
                        float b0 = bs[col], b1 = bs[col + 1];
                        v0.x += b0; v0.y += b1;
                        v1.x += b0; v1.y += b1;
                        *(float2*)(out_mean + (size_t)r0 * YD + col)       = v0;
                        *(float2*)(out_mean + (size_t)(r0 + 8) * YD + col) = v1;
                    } else {
                        v0.x = __logf(v0.x); v0.y = __logf(v0.y);
                        v1.x = __logf(v1.x); v1.y = __logf(v1.y);
                        *(float2*)(out_logv + (size_t)r0 * YD + col)       = v0;
                        *(float2*)(out_logv + (size_t)(r0 + 8) * YD + col) = v1;
                    }
                }
            }
            __syncthreads();  // buffer (nc&1) may be overwritten next iter
        }
    }
}

// ---------------------------------------------------------------------------
// Launch
// ---------------------------------------------------------------------------
extern "C" void kernel_launch(void* const* d_in, const int* in_sizes, int n_in,
                              void* d_out, int out_size) {
    const float* mean   = (const float*)d_in[0];
    const float* logvar = (const float*)d_in[1];
    const float* W      = (const float*)d_in[2];
    const float* bias   = (const float*)d_in[3];

    const int B = in_sizes[0] / XD;   // 131072
    float* out_mean = (float*)d_out;
    float* out_logv = out_mean + (size_t)B * YD;

    prep_w_kernel<<<(YD * (XD / 2) + TPB - 1) / TPB, TPB>>>(W);

    cudaFuncSetAttribute(decoder_kernel,
                         cudaFuncAttributeMaxDynamicSharedMemorySize, SMEM_SIZE);
    decoder_kernel<<<B / MT, TPB, SMEM_SIZE>>>(mean, logvar, bias,
                                               out_mean, out_logv);
}

// round 4
// speedup vs baseline: 1.1532x; 1.1532x over previous
#include <cuda_runtime.h>
#include <cuda_bf16.h>
#include <cstdint>
#include <cstddef>

// ============================================================================
// LinearDecoder: out_mean = mean @ W^T + b ; out_logv = log( exp(logvar) @ (W*W)^T )
// B=131072, X=128, Y=512.  Plain-sm_103 PTX (no tcgen05 in this harness).
// mma.sync.m16n8k16 bf16 with fp32 hi/lo splitting (hh+hl+lh).
// Round-4: B operands pre-baked in MMA-fragment order in gmem (LDG.128,
// L1/L2 resident) -> no B smem, no cp.async, 2 CTAs/SM, sync-free mainloop.
// ============================================================================

static constexpr int XD  = 128;   // K
static constexpr int YD  = 512;   // N total
static constexpr int MT  = 128;   // M rows per CTA
static constexpr int TPB = 256;

// B fragments: [kind: Whi,Wlo,W2hi,W2lo][h: 32-col slice 0..15][ks 0..7]
//              [p 0..1][lane 0..31][16B = b0,b1 of tiles ni=2p, 2p+1]
__device__ __align__(16) unsigned char g_Bfrag[4][16][8][2][32][16];

// SMEM: bias + A hi/lo tiles only
static constexpr int OFF_BIAS = 0;                 // 512 floats
static constexpr int OFF_AH   = 4096;              // A hi tile 32KB
static constexpr int OFF_AL   = OFF_AH + 32768;    // A lo tile 32KB
static constexpr int SMEM_SIZE = OFF_AL + 32768;   // 69632 B -> 2+ CTAs/SM

// ---------------------------------------------------------------------------
// helpers
// ---------------------------------------------------------------------------
__device__ __forceinline__ uint32_t smem_u32(const void* p) {
    uint32_t a;
    asm("{ .reg .u64 t; cvta.to.shared.u64 t, %1; cvt.u32.u64 %0, t; }"
        : "=r"(a) : "l"(p));
    return a;
}

// A tile: 128 rows x 256B, 16B chunks XOR-swizzled with (r&7)
__device__ __forceinline__ uint32_t tile_off(int r, int k0) {
    uint32_t ck = (uint32_t)(k0 >> 3) ^ (uint32_t)(r & 7);
    return (uint32_t)r * 256u + ck * 16u + (uint32_t)(k0 & 7) * 2u;
}

__device__ __forceinline__ float bf16rt(float x) {
    return __bfloat162float(__float2bfloat16(x));
}

__device__ __forceinline__ uint32_t pack2(float a, float b) {
    __nv_bfloat162 t = __floats2bfloat162_rn(a, b);
    return *reinterpret_cast<uint32_t*>(&t);
}

__device__ __forceinline__ void ldsm4(uint32_t* r, uint32_t addr) {
    asm volatile("ldmatrix.sync.aligned.m8n8.x4.shared.b16 {%0,%1,%2,%3}, [%4];"
                 : "=r"(r[0]), "=r"(r[1]), "=r"(r[2]), "=r"(r[3]) : "r"(addr));
}

__device__ __forceinline__ void mma16816(float* c, const uint32_t* a,
                                         uint32_t b0, uint32_t b1) {
    asm volatile(
        "mma.sync.aligned.m16n8k16.row.col.f32.bf16.bf16.f32 "
        "{%0,%1,%2,%3}, {%4,%5,%6,%7}, {%8,%9}, {%0,%1,%2,%3};"
        : "+f"(c[0]), "+f"(c[1]), "+f"(c[2]), "+f"(c[3])
        : "r"(a[0]), "r"(a[1]), "r"(a[2]), "r"(a[3]), "r"(b0), "r"(b1));
}

// ---------------------------------------------------------------------------
// Prep kernel: bake W / W*W hi/lo into MMA-fragment order.
// PTX m16n8k16 B layout: lane l holds b0 = B[k0..k0+1][n], b1 = B[k0+8..k0+9][n]
// with n = l/4, k0 = (l%4)*2 (within the 16x8 tile).
// ---------------------------------------------------------------------------
__global__ void prep_w_kernel(const float* __restrict__ W) {
    int id = blockIdx.x * blockDim.x + threadIdx.x;   // 0 .. 16383
    if (id >= 2 * 16 * 8 * 2 * 32) return;
    const int lane   = id & 31;
    const int p      = (id >> 5) & 1;
    const int ks     = (id >> 6) & 7;
    const int h      = (id >> 9) & 15;
    const int branch = id >> 13;                      // 0 = W, 1 = W*W

    uint32_t hi[4], lo[4];
    #pragma unroll
    for (int w = 0; w < 4; ++w) {
        int ni = 2 * p + (w >> 1);
        int n  = h * 32 + ni * 8 + (lane >> 2);
        int k  = ks * 16 + (w & 1) * 8 + (lane & 3) * 2;
        float w0 = W[n * XD + k];
        float w1 = W[n * XD + k + 1];
        if (branch) { w0 *= w0; w1 *= w1; }
        float h0 = bf16rt(w0), h1 = bf16rt(w1);
        hi[w] = pack2(h0, h1);
        lo[w] = pack2(w0 - h0, w1 - h1);
    }
    *(uint4*)&g_Bfrag[branch * 2][h][ks][p][lane][0] =
        make_uint4(hi[0], hi[1], hi[2], hi[3]);
    *(uint4*)&g_Bfrag[branch * 2 + 1][h][ks][p][lane][0] =
        make_uint4(lo[0], lo[1], lo[2], lo[3]);
}

// ---------------------------------------------------------------------------
// Main kernel: CTA = 128 batch rows; warp = 32(M) x 32(N) of each 64-col chunk
// ---------------------------------------------------------------------------
__global__ void __launch_bounds__(TPB, 2)
decoder_kernel(const float* __restrict__ mean, const float* __restrict__ logvar,
               const float* __restrict__ bias,
               float* __restrict__ out_mean, float* __restrict__ out_logv) {
    extern __shared__ __align__(16) char smem[];
    const uint32_t sb = smem_u32(smem);
    const int tid = threadIdx.x;
    const int t   = tid & 31;
    const int wid = tid >> 5;
    const int wm  = wid & 3;       // M group: rows wm*32 .. wm*32+31
    const int wn  = wid >> 2;      // N half within 64-col chunk
    const int row0 = blockIdx.x * MT;

    for (int i = tid; i < YD; i += TPB)
        ((float*)(smem + OFF_BIAS))[i] = bias[i];

    // Precompute A ldsm addresses (row fixed per thread per mi)
    uint32_t a_off[2];
    #pragma unroll
    for (int mi = 0; mi < 2; ++mi) {
        uint32_t row = (uint32_t)(wm * 32 + mi * 16 + (t & 15));
        a_off[mi] = row * 256u + (((uint32_t)(t >> 4) ^ (row & 7u)) << 4);
        // per-ks advance handled by XOR of chunk index: ck = 2ks + (t>>4)
    }

    for (int branch = 0; branch < 2; ++branch) {
        if (branch) __syncthreads();   // A tiles about to be rewritten
        // ---- A conversion -> hi/lo bf16 swizzled tiles ----
        const float* src = branch ? logvar : mean;
        for (int idx = tid; idx < MT * (XD / 2); idx += TPB) {
            int r  = idx >> 6;
            int k0 = (idx & 63) * 2;
            float2 v = *(const float2*)(src + (size_t)(row0 + r) * XD + k0);
            float v0 = v.x, v1 = v.y;
            if (branch) { v0 = __expf(v0); v1 = __expf(v1); }
            uint32_t sw = tile_off(r, k0);
            float h0 = bf16rt(v0), h1 = bf16rt(v1);
            *(uint32_t*)(smem + OFF_AH + sw) = pack2(h0, h1);
            *(uint32_t*)(smem + OFF_AL + sw) = pack2(v0 - h0, v1 - h1);
        }
        __syncthreads();

        for (int nc = 0; nc < 8; ++nc) {
            const int h = nc * 2 + wn;
            // uint4 element index: (((kind*16 + h)*8 + ks)*2 + p)*32 + lane
            const uint4* bH = (const uint4*)g_Bfrag +
                (size_t)((branch * 2) * 16 + h) * (8 * 2 * 32) + t;
            const uint4* bL = (const uint4*)g_Bfrag +
                (size_t)((branch * 2 + 1) * 16 + h) * (8 * 2 * 32) + t;

            float c[2][4][4] = {};

            #pragma unroll
            for (int ks = 0; ks < 8; ++ks) {
                // B fragments via coalesced LDG.128 (L1-resident)
                uint4 h0 = bH[ks * 64];        // p=0: tiles ni 0,1
                uint4 h1 = bH[ks * 64 + 32];   // p=1: tiles ni 2,3
                uint4 l0 = bL[ks * 64];
                uint4 l1 = bL[ks * 64 + 32];
                const uint32_t bh[8] = {h0.x, h0.y, h0.z, h0.w,
                                        h1.x, h1.y, h1.z, h1.w};
                const uint32_t bl[8] = {l0.x, l0.y, l0.z, l0.w,
                                        l1.x, l1.y, l1.z, l1.w};
                // A fragments via ldmatrix
                uint32_t ah[8], al[8];
                const uint32_t kxor = ((uint32_t)(2 * ks) << 4);
                #pragma unroll
                for (int mi = 0; mi < 2; ++mi) {
                    uint32_t off = a_off[mi] ^ kxor;
                    ldsm4(&ah[mi * 4], sb + OFF_AH + off);
                    ldsm4(&al[mi * 4], sb + OFF_AL + off);
                }
                // split terms: hh, hl, lh
                #pragma unroll
                for (int mi = 0; mi < 2; ++mi) {
                    #pragma unroll
                    for (int ni = 0; ni < 4; ++ni) {
                        mma16816(c[mi][ni], &ah[mi * 4], bh[ni * 2], bh[ni * 2 + 1]);
                        mma16816(c[mi][ni], &ah[mi * 4], bl[ni * 2], bl[ni * 2 + 1]);
                        mma16816(c[mi][ni], &al[mi * 4], bh[ni * 2], bh[ni * 2 + 1]);
                    }
                }
            }

            // ---- epilogue (no syncthreads needed: A tile untouched) ----
            const float* bs = (const float*)(smem + OFF_BIAS);
            #pragma unroll
            for (int mi = 0; mi < 2; ++mi) {
                const int r0 = row0 + wm * 32 + mi * 16 + (t >> 2);
                #pragma unroll
                for (int ni = 0; ni < 4; ++ni) {
                    const int col = nc * 64 + wn * 32 + ni * 8 + (t & 3) * 2;
                    float2 v0, v1;
                    v0.x = c[mi][ni][0]; v0.y = c[mi][ni][1];
                    v1.x = c[mi][ni][2]; v1.y = c[mi][ni][3];
                    if (branch == 0) {
                        float b0 = bs[col], b1 = bs[col + 1];
                        v0.x += b0; v0.y += b1;
                        v1.x += b0; v1.y += b1;
                        *(float2*)(out_mean + (size_t)r0 * YD + col)       = v0;
                        *(float2*)(out_mean + (size_t)(r0 + 8) * YD + col) = v1;
                    } else {
                        v0.x = __logf(v0.x); v0.y = __logf(v0.y);
                        v1.x = __logf(v1.x); v1.y = __logf(v1.y);
                        *(float2*)(out_logv + (size_t)r0 * YD + col)       = v0;
                        *(float2*)(out_logv + (size_t)(r0 + 8) * YD + col) = v1;
                    }
                }
            }
        }
    }
}

// ---------------------------------------------------------------------------
// Launch
// ---------------------------------------------------------------------------
extern "C" void kernel_launch(void* const* d_in, const int* in_sizes, int n_in,
                              void* d_out, int out_size) {
    const float* mean   = (const float*)d_in[0];
    const float* logvar = (const float*)d_in[1];
    const float* W      = (const float*)d_in[2];
    const float* bias   = (const float*)d_in[3];

    const int B = in_sizes[0] / XD;   // 131072
    float* out_mean = (float*)d_out;
    float* out_logv = out_mean + (size_t)B * YD;

    prep_w_kernel<<<64, TPB>>>(W);

    cudaFuncSetAttribute(decoder_kernel,
                         cudaFuncAttributeMaxDynamicSharedMemorySize, SMEM_SIZE);
    decoder_kernel<<<B / MT, TPB, SMEM_SIZE>>>(mean, logvar, bias,
                                               out_mean, out_logv);
}